// round 13
// baseline (speedup 1.0000x reference)
#include <cuda_runtime.h>
#include <cuda_bf16.h>
#include <cstdint>
#include <math.h>

#define BATCH 4
#define SEQ   2048
#define DMODEL 1024

// smem: BK=128 int8 -> 128B rows; planes A0|A1|B0|B1 16KB each; 3 stages
#define PLANE_BYTES  16384
#define STAGE_BYTES  (4 * PLANE_BYTES)      // 64KB
#define NSTAGE       3
#define SMEM_TOTAL   (NSTAGE * STAGE_BYTES) // 192KB
#define NTHREADS     256

// ======================= scratch ============================================
__device__ __align__(16) char g_E0[BATCH * SEQ * DMODEL];
__device__ __align__(16) char g_E1[BATCH * SEQ * DMODEL];
__device__ __align__(16) char g_W0[3 * DMODEL * DMODEL];
__device__ __align__(16) char g_W1[3 * DMODEL * DMODEL];
__device__ __align__(16) char g_Q0[BATCH * SEQ * DMODEL];
__device__ __align__(16) char g_Q1[BATCH * SEQ * DMODEL];
__device__ __align__(16) char g_K0[BATCH * SEQ * DMODEL];
__device__ __align__(16) char g_K1[BATCH * SEQ * DMODEL];
__device__ __align__(16) char g_Vt0[BATCH * DMODEL * SEQ];   // [b][d][s]
__device__ __align__(16) char g_Vt1[BATCH * DMODEL * SEQ];
__device__ __align__(16) char g_P0[BATCH * SEQ * SEQ];
__device__ __align__(16) char g_P1[BATCH * SEQ * SEQ];
__device__ __align__(16) float g_Qf[BATCH * SEQ * DMODEL];
__device__ __align__(16) float g_Kf[BATCH * SEQ * DMODEL];
__device__ __align__(16) float g_Vtf[BATCH * DMODEL * SEQ];
__device__ float g_sE[BATCH * SEQ];
__device__ float g_sW[3 * DMODEL];
__device__ float g_sQ[BATCH * SEQ];
__device__ float g_sK[BATCH * SEQ];
__device__ float g_sVt[BATCH * DMODEL];
__device__ float g_sP[BATCH * SEQ];
__device__ float g_mags[BATCH * SEQ];
__device__ float g_thresh;

__device__ __forceinline__ uint32_t smem_u32(const void* p) {
    uint32_t a;
    asm("{ .reg .u64 t; cvta.to.shared.u64 t, %1; cvt.u32.u64 %0, t; }" : "=r"(a) : "l"(p));
    return a;
}
__device__ __forceinline__ void cp16(uint32_t dst, const void* src) {
    asm volatile("cp.async.cg.shared.global [%0], [%1], 16;" :: "r"(dst), "l"(src));
}
#define CP_COMMIT() asm volatile("cp.async.commit_group;" ::: "memory")
#define CP_WAIT1()  asm volatile("cp.async.wait_group 1;" ::: "memory")

__device__ __forceinline__ void ldm4(uint32_t f[4], uint32_t addr) {
    asm volatile("ldmatrix.sync.aligned.m8n8.x4.shared.b16 {%0,%1,%2,%3}, [%4];"
        : "=r"(f[0]), "=r"(f[1]), "=r"(f[2]), "=r"(f[3]) : "r"(addr));
}
__device__ __forceinline__ void imma(int c[4], const uint32_t a[4],
                                     uint32_t b0, uint32_t b1) {
    asm volatile(
        "mma.sync.aligned.m16n8k32.row.col.s32.s8.s8.s32 "
        "{%0,%1,%2,%3}, {%4,%5,%6,%7}, {%8,%9}, {%0,%1,%2,%3};"
        : "+r"(c[0]), "+r"(c[1]), "+r"(c[2]), "+r"(c[3])
        : "r"(a[0]), "r"(a[1]), "r"(a[2]), "r"(a[3]), "r"(b0), "r"(b1));
}

__device__ __forceinline__ void quant2(float x, float inv, char& q0, char& q1) {
    float t = x * inv;
    int a = __float2int_rn(t);
    int b = __float2int_rn((t - (float)a) * 128.0f);
    q0 = (char)a;
    q1 = (char)b;
}

// ======================= quantize rows ======================================
__global__ void quant_rows(const float* __restrict__ src, char* __restrict__ L0,
                           char* __restrict__ L1, float* __restrict__ scl, int C) {
    int row = blockIdx.x, tid = threadIdx.x;
    const float4* p = (const float4*)(src + (size_t)row * C);
    int n4 = C >> 2;
    float mx = 0.0f;
    for (int i = tid; i < n4; i += 256) {
        float4 v = p[i];
        mx = fmaxf(mx, fmaxf(fmaxf(fabsf(v.x), fabsf(v.y)),
                             fmaxf(fabsf(v.z), fabsf(v.w))));
    }
    __shared__ float sm[256];
    sm[tid] = mx;
    __syncthreads();
    for (int off = 128; off > 0; off >>= 1) {
        if (tid < off) sm[tid] = fmaxf(sm[tid], sm[tid + off]);
        __syncthreads();
    }
    float s = sm[0] * (1.0f / 127.0f);
    float inv = (s > 0.0f) ? 1.0f / s : 0.0f;
    if (tid == 0) scl[row] = (s > 0.0f) ? s : 1.0f;
    char* l0 = L0 + (size_t)row * C;
    char* l1 = L1 + (size_t)row * C;
    for (int i = tid; i < n4; i += 256) {
        float4 v = p[i];
        char a0, a1, b0, b1, c0, c1, d0, d1;
        quant2(v.x, inv, a0, a1); quant2(v.y, inv, b0, b1);
        quant2(v.z, inv, c0, c1); quant2(v.w, inv, d0, d1);
        ((char4*)l0)[i] = make_char4(a0, b0, c0, d0);
        ((char4*)l1)[i] = make_char4(a1, b1, c1, d1);
    }
}

// ======================= mags / thresh ======================================
__global__ void mags_kernel(const float* __restrict__ E) {
    int row = blockIdx.x;
    const float4* p = (const float4*)(E + (size_t)row * DMODEL);
    int tid = threadIdx.x;
    float4 v = p[tid];
    float s = v.x * v.x + v.y * v.y + v.z * v.z + v.w * v.w;
    __shared__ float sm[256];
    sm[tid] = s;
    __syncthreads();
    for (int off = 128; off > 0; off >>= 1) {
        if (tid < off) sm[tid] += sm[tid + off];
        __syncthreads();
    }
    if (tid == 0) g_mags[row] = sqrtf(sm[0]);
}

__global__ void thresh_kernel() {
    int tid = threadIdx.x;
    __shared__ double sd[256];
    double total = 0.0;
    for (int b = 0; b < BATCH; b++) {
        double local = 0.0;
        for (int i = tid; i < SEQ; i += 256) local += (double)g_mags[b * SEQ + i];
        sd[tid] = local;
        __syncthreads();
        for (int off = 128; off > 0; off >>= 1) {
            if (tid < off) sd[tid] += sd[tid + off];
            __syncthreads();
        }
        if (tid == 0) total += sd[0] * sd[0];
        __syncthreads();
    }
    if (tid == 0) g_thresh = (float)(total / ((double)BATCH * SEQ * SEQ));
}

// ======================= softmax (+ inline P quantization) ==================
__global__ void softmax_kernel(float* __restrict__ w) {
    size_t row = blockIdx.x;
    float4* p = (float4*)(w + row * SEQ);
    int tid = threadIdx.x;
    float4 v0 = p[tid];
    float4 v1 = p[tid + 256];
    float m = fmaxf(fmaxf(fmaxf(v0.x, v0.y), fmaxf(v0.z, v0.w)),
                    fmaxf(fmaxf(v1.x, v1.y), fmaxf(v1.z, v1.w)));
    __shared__ float sm[256];
    sm[tid] = m;
    __syncthreads();
    for (int off = 128; off > 0; off >>= 1) {
        if (tid < off) sm[tid] = fmaxf(sm[tid], sm[tid + off]);
        __syncthreads();
    }
    m = sm[0];
    __syncthreads();
    v0.x = expf(v0.x - m); v0.y = expf(v0.y - m);
    v0.z = expf(v0.z - m); v0.w = expf(v0.w - m);
    v1.x = expf(v1.x - m); v1.y = expf(v1.y - m);
    v1.z = expf(v1.z - m); v1.w = expf(v1.w - m);
    float s = v0.x + v0.y + v0.z + v0.w + v1.x + v1.y + v1.z + v1.w;
    sm[tid] = s;
    __syncthreads();
    for (int off = 128; off > 0; off >>= 1) {
        if (tid < off) sm[tid] += sm[tid + off];
        __syncthreads();
    }
    float inv = 1.0f / sm[0];
    if (tid == 0) g_sP[row] = inv * (1.0f / 127.0f);

    char q0[8], q1[8];
    quant2(v0.x * 127.0f, 1.0f, q0[0], q1[0]);
    quant2(v0.y * 127.0f, 1.0f, q0[1], q1[1]);
    quant2(v0.z * 127.0f, 1.0f, q0[2], q1[2]);
    quant2(v0.w * 127.0f, 1.0f, q0[3], q1[3]);
    quant2(v1.x * 127.0f, 1.0f, q0[4], q1[4]);
    quant2(v1.y * 127.0f, 1.0f, q0[5], q1[5]);
    quant2(v1.z * 127.0f, 1.0f, q0[6], q1[6]);
    quant2(v1.w * 127.0f, 1.0f, q0[7], q1[7]);
    ((char4*)(g_P0 + row * SEQ))[tid] = make_char4(q0[0], q0[1], q0[2], q0[3]);
    ((char4*)(g_P1 + row * SEQ))[tid] = make_char4(q1[0], q1[1], q1[2], q1[3]);
    ((char4*)(g_P0 + row * SEQ))[tid + 256] = make_char4(q0[4], q0[5], q0[6], q0[7]);
    ((char4*)(g_P1 + row * SEQ))[tid + 256] = make_char4(q1[4], q1[5], q1[6], q1[7]);

    v0.x *= inv; v0.y *= inv; v0.z *= inv; v0.w *= inv;
    v1.x *= inv; v1.y *= inv; v1.z *= inv; v1.w *= inv;
    p[tid] = v0;
    p[tid + 256] = v1;
}

// ======================= pipelined IMMA GEMM core ===========================
// C[128x128]/CTA, 256 threads, 8 warps (2m x 4n) each 64x32, BK=128, 3 stages.
__device__ __forceinline__ void load_stage(
    uint32_t sb, int slot, int row, int hs,
    const char* __restrict__ A0, const char* __restrict__ A1,
    const char* __restrict__ B0, const char* __restrict__ B1,
    int lda, int ldb, int m0, int n0, int k0)
{
    uint32_t drow = sb + (uint32_t)slot * STAGE_BYTES + (uint32_t)row * 128;
    const char* a0 = A0 + (size_t)(m0 + row) * lda + k0;
    const char* a1 = A1 + (size_t)(m0 + row) * lda + k0;
    const char* b0 = B0 + (size_t)(n0 + row) * ldb + k0;
    const char* b1 = B1 + (size_t)(n0 + row) * ldb + k0;
    #pragma unroll
    for (int i = 0; i < 4; i++) {
        int seg = hs * 4 + i;
        uint32_t sw = (uint32_t)((seg ^ (row & 7)) * 16);
        cp16(drow + sw,                   a0 + seg * 16);
        cp16(drow + sw + PLANE_BYTES,     a1 + seg * 16);
        cp16(drow + sw + 2 * PLANE_BYTES, b0 + seg * 16);
        cp16(drow + sw + 3 * PLANE_BYTES, b1 + seg * 16);
    }
}

__device__ __forceinline__ void gemm_run(
    const char* __restrict__ A0, const char* __restrict__ A1,
    const char* __restrict__ B0, const char* __restrict__ B1,
    int lda, int ldb, int K, int m0, int n0,
    int acc0[4][4][4], int accX[4][4][4])
{
    extern __shared__ __align__(16) char smem[];
    uint32_t sb = smem_u32(smem);
    int tid = threadIdx.x, lane = tid & 31, warp = tid >> 5;
    int wm = (warp >> 2) * 64, wn = (warp & 3) * 32;
    int row = tid >> 1, hs = tid & 1;
    int g = lane >> 3, r = lane & 7;
    int rb = (g & 1) * 8 + r, hsel = g >> 1;

    int NC = K >> 7;   // BK=128 int8
    #pragma unroll
    for (int s = 0; s < NSTAGE - 1; s++) {
        load_stage(sb, s, row, hs, A0, A1, B0, B1, lda, ldb, m0, n0, s * 128);
        CP_COMMIT();
    }

    uint32_t arow = (uint32_t)((wm + rb) * 128);
    uint32_t brow = (uint32_t)((wn + rb) * 128);

    for (int c = 0; c < NC; c++) {
        CP_WAIT1();
        __syncthreads();
        if (c + 2 < NC) {
            load_stage(sb, (c + 2) % NSTAGE, row, hs, A0, A1, B0, B1,
                       lda, ldb, m0, n0, (c + 2) * 128);
            CP_COMMIT();
        }
        uint32_t st = sb + (uint32_t)(c % NSTAGE) * STAGE_BYTES;
        #pragma unroll
        for (int kb = 0; kb < 4; kb++) {
            uint32_t segoff = (uint32_t)((((kb * 2) | hsel) ^ r) * 16);
            uint32_t a0f[4][4], a1f[4][4], b0f[2][4], b1f[2][4];
            #pragma unroll
            for (int nb = 0; nb < 2; nb++) {
                uint32_t bd = st + 2 * PLANE_BYTES + brow + (uint32_t)(nb * 16 * 128) + segoff;
                ldm4(b0f[nb], bd);
                ldm4(b1f[nb], bd + PLANE_BYTES);
            }
            #pragma unroll
            for (int mi = 0; mi < 4; mi++) {
                uint32_t ad = st + arow + (uint32_t)(mi * 16 * 128) + segoff;
                ldm4(a0f[mi], ad);
                ldm4(a1f[mi], ad + PLANE_BYTES);
            }
            #pragma unroll
            for (int mi = 0; mi < 4; mi++)
                #pragma unroll
                for (int nb = 0; nb < 2; nb++)
                    #pragma unroll
                    for (int s = 0; s < 2; s++) {
                        int ni = nb * 2 + s;
                        imma(acc0[mi][ni], a0f[mi], b0f[nb][s], b0f[nb][s + 2]);
                        imma(accX[mi][ni], a0f[mi], b1f[nb][s], b1f[nb][s + 2]);
                        imma(accX[mi][ni], a1f[mi], b0f[nb][s], b0f[nb][s + 2]);
                    }
        }
    }
}

#define COMBINE(mi, ni, j) ((float)acc0[mi][ni][j] + (float)accX[mi][ni][j] * 0.0078125f)

// ======================= GEMM kernels =======================================
__global__ void __launch_bounds__(NTHREADS, 1) qkv_tc() {
    int z = blockIdx.z;
    const char* Bw0 = g_W0 + (size_t)z * DMODEL * DMODEL;
    const char* Bw1 = g_W1 + (size_t)z * DMODEL * DMODEL;
    int m0 = blockIdx.y * 128, n0 = blockIdx.x * 128;
    int acc0[4][4][4] = {}, accX[4][4][4] = {};
    gemm_run(g_E0, g_E1, Bw0, Bw1, DMODEL, DMODEL, DMODEL, m0, n0, acc0, accX);

    int lane = threadIdx.x & 31, warp = threadIdx.x >> 5;
    int wm = (warp >> 2) * 64, wn = (warp & 3) * 32;
    #pragma unroll
    for (int mi = 0; mi < 4; mi++)
        #pragma unroll
        for (int h = 0; h < 2; h++) {
            int rg = m0 + wm + mi * 16 + h * 8 + (lane >> 2);
            float sa = g_sE[rg];
            #pragma unroll
            for (int ni = 0; ni < 4; ni++) {
                int col = n0 + wn + ni * 8 + (lane & 3) * 2;
                float sb0 = g_sW[z * DMODEL + col];
                float sb1 = g_sW[z * DMODEL + col + 1];
                float x0 = sa * sb0 * COMBINE(mi, ni, h * 2);
                float x1 = sa * sb1 * COMBINE(mi, ni, h * 2 + 1);
                if (z == 2) {
                    int b = rg >> 11, s = rg & (SEQ - 1);
                    float* vb = g_Vtf + (size_t)b * DMODEL * SEQ;
                    vb[(size_t)col * SEQ + s] = x0;
                    vb[(size_t)(col + 1) * SEQ + s] = x1;
                } else {
                    float* C = (z == 0) ? g_Qf : g_Kf;
                    *(float2*)&C[(size_t)rg * DMODEL + col] = make_float2(x0, x1);
                }
            }
        }
}

__global__ void __launch_bounds__(NTHREADS, 1) scores_tc(
    const float* __restrict__ intent_bias, const int* __restrict__ mask,
    float* __restrict__ wts)
{
    int b = blockIdx.z;
    size_t off = (size_t)b * SEQ * DMODEL;
    int m0 = blockIdx.y * 128, n0 = blockIdx.x * 128;
    int acc0[4][4][4] = {}, accX[4][4][4] = {};
    gemm_run(g_Q0 + off, g_Q1 + off, g_K0 + off, g_K1 + off,
             DMODEL, DMODEL, DMODEL, m0, n0, acc0, accX);

    int lane = threadIdx.x & 31, warp = threadIdx.x >> 5;
    int wm = (warp >> 2) * 64, wn = (warp & 3) * 32;
    float th = g_thresh;
    float bias = intent_bias[0];
    #pragma unroll
    for (int mi = 0; mi < 4; mi++)
        #pragma unroll
        for (int h = 0; h < 2; h++) {
            int q = m0 + wm + mi * 16 + h * 8 + (lane >> 2);
            float mq = g_mags[b * SEQ + q];
            float sa = g_sQ[b * SEQ + q] * 0.03125f;
            size_t rb = ((size_t)b * SEQ + q) * SEQ;
            #pragma unroll
            for (int ni = 0; ni < 4; ni++) {
                int col = n0 + wn + ni * 8 + (lane & 3) * 2;
                float x0 = sa * g_sK[b * SEQ + col] * COMBINE(mi, ni, h * 2);
                float x1 = sa * g_sK[b * SEQ + col + 1] * COMBINE(mi, ni, h * 2 + 1);
                float mk0 = g_mags[b * SEQ + col];
                float mk1 = g_mags[b * SEQ + col + 1];
                if (mq * mk0 > th) x0 += bias;
                if (mq * mk1 > th) x1 += bias;
                int2 mv = *(const int2*)&mask[rb + col];
                if (mv.x == 0) x0 = -1e9f;
                if (mv.y == 0) x1 = -1e9f;
                *(float2*)&wts[rb + col] = make_float2(x0, x1);
            }
        }
}

__global__ void __launch_bounds__(NTHREADS, 1) av_tc(float* __restrict__ att) {
    int b = blockIdx.z;
    size_t po = (size_t)b * SEQ * SEQ;
    size_t vo = (size_t)b * DMODEL * SEQ;
    int m0 = blockIdx.y * 128, n0 = blockIdx.x * 128;
    int acc0[4][4][4] = {}, accX[4][4][4] = {};
    gemm_run(g_P0 + po, g_P1 + po, g_Vt0 + vo, g_Vt1 + vo,
             SEQ, SEQ, SEQ, m0, n0, acc0, accX);

    int lane = threadIdx.x & 31, warp = threadIdx.x >> 5;
    int wm = (warp >> 2) * 64, wn = (warp & 3) * 32;
    #pragma unroll
    for (int mi = 0; mi < 4; mi++)
        #pragma unroll
        for (int h = 0; h < 2; h++) {
            int s = m0 + wm + mi * 16 + h * 8 + (lane >> 2);
            float sa = g_sP[b * SEQ + s];
            #pragma unroll
            for (int ni = 0; ni < 4; ni++) {
                int col = n0 + wn + ni * 8 + (lane & 3) * 2;
                float x0 = sa * g_sVt[b * DMODEL + col] * COMBINE(mi, ni, h * 2);
                float x1 = sa * g_sVt[b * DMODEL + col + 1] * COMBINE(mi, ni, h * 2 + 1);
                *(float2*)&att[((size_t)b * SEQ + s) * DMODEL + col] =
                    make_float2(x0, x1);
            }
        }
}

// ======================= launch =============================================
extern "C" void kernel_launch(void* const* d_in, const int* in_sizes, int n_in,
                              void* d_out, int out_size)
{
    (void)in_sizes; (void)n_in; (void)out_size;
    const float* E    = (const float*)d_in[0];
    const float* Wq   = (const float*)d_in[1];
    const float* Wk   = (const float*)d_in[2];
    const float* Wv   = (const float*)d_in[3];
    const float* bias = (const float*)d_in[4];
    const int*   mask = (const int*)d_in[5];

    float* out = (float*)d_out;
    float* att = out;                                  // [B,S,D]
    float* wts = out + (size_t)BATCH * SEQ * DMODEL;   // [B,S,S]

    cudaFuncSetAttribute(qkv_tc,    cudaFuncAttributeMaxDynamicSharedMemorySize, SMEM_TOTAL);
    cudaFuncSetAttribute(scores_tc, cudaFuncAttributeMaxDynamicSharedMemorySize, SMEM_TOTAL);
    cudaFuncSetAttribute(av_tc,     cudaFuncAttributeMaxDynamicSharedMemorySize, SMEM_TOTAL);

    char *E0, *E1, *W0, *W1, *Q0, *Q1, *K0, *K1, *V0, *V1;
    float *sE, *sW, *sQ, *sK, *sV, *Qf, *Kf, *Vf;
    cudaGetSymbolAddress((void**)&E0, g_E0); cudaGetSymbolAddress((void**)&E1, g_E1);
    cudaGetSymbolAddress((void**)&W0, g_W0); cudaGetSymbolAddress((void**)&W1, g_W1);
    cudaGetSymbolAddress((void**)&Q0, g_Q0); cudaGetSymbolAddress((void**)&Q1, g_Q1);
    cudaGetSymbolAddress((void**)&K0, g_K0); cudaGetSymbolAddress((void**)&K1, g_K1);
    cudaGetSymbolAddress((void**)&V0, g_Vt0); cudaGetSymbolAddress((void**)&V1, g_Vt1);
    cudaGetSymbolAddress((void**)&sE, g_sE); cudaGetSymbolAddress((void**)&sW, g_sW);
    cudaGetSymbolAddress((void**)&sQ, g_sQ); cudaGetSymbolAddress((void**)&sK, g_sK);
    cudaGetSymbolAddress((void**)&sV, g_sVt);
    cudaGetSymbolAddress((void**)&Qf, g_Qf); cudaGetSymbolAddress((void**)&Kf, g_Kf);
    cudaGetSymbolAddress((void**)&Vf, g_Vtf);

    quant_rows<<<BATCH * SEQ, 256>>>(E, E0, E1, sE, DMODEL);
    quant_rows<<<DMODEL, 256>>>(Wq, W0, W1, sW, DMODEL);
    quant_rows<<<DMODEL, 256>>>(Wk, W0 + (size_t)DMODEL * DMODEL,
                                W1 + (size_t)DMODEL * DMODEL, sW + DMODEL, DMODEL);
    quant_rows<<<DMODEL, 256>>>(Wv, W0 + 2 * (size_t)DMODEL * DMODEL,
                                W1 + 2 * (size_t)DMODEL * DMODEL, sW + 2 * DMODEL, DMODEL);

    mags_kernel<<<BATCH * SEQ, 256>>>(E);
    thresh_kernel<<<1, 256>>>();

    dim3 gQKV(DMODEL / 128, (BATCH * SEQ) / 128, 3);
    qkv_tc<<<gQKV, NTHREADS, SMEM_TOTAL>>>();

    quant_rows<<<BATCH * SEQ, 256>>>(Qf, Q0, Q1, sQ, DMODEL);
    quant_rows<<<BATCH * SEQ, 256>>>(Kf, K0, K1, sK, DMODEL);
    quant_rows<<<BATCH * DMODEL, 256>>>(Vf, V0, V1, sV, SEQ);

    dim3 gS(SEQ / 128, SEQ / 128, BATCH);
    scores_tc<<<gS, NTHREADS, SMEM_TOTAL>>>(bias, mask, wts);

    softmax_kernel<<<BATCH * SEQ, 256>>>(wts);

    dim3 gAV(DMODEL / 128, SEQ / 128, BATCH);
    av_tc<<<gAV, NTHREADS, SMEM_TOTAL>>>(att);
}

// round 14
// speedup vs baseline: 1.1251x; 1.1251x over previous
#include <cuda_runtime.h>
#include <cuda_bf16.h>
#include <cstdint>
#include <math.h>

#define BATCH 4
#define SEQ   2048
#define DMODEL 1024

// smem: BK=128 int8 -> 128B rows; planes A0|A1|B0|B1 16KB each; 3 stages
#define PLANE_BYTES  16384
#define STAGE_BYTES  (4 * PLANE_BYTES)      // 64KB
#define NSTAGE       3
#define SMEM_TOTAL   (NSTAGE * STAGE_BYTES) // 192KB
#define NTHREADS     512
#define PGRID        148                    // persistent CTAs (1/SM)

// ======================= scratch ============================================
__device__ __align__(16) char g_E0[BATCH * SEQ * DMODEL];
__device__ __align__(16) char g_E1[BATCH * SEQ * DMODEL];
__device__ __align__(16) char g_W0[3 * DMODEL * DMODEL];
__device__ __align__(16) char g_W1[3 * DMODEL * DMODEL];
__device__ __align__(16) char g_Q0[BATCH * SEQ * DMODEL];
__device__ __align__(16) char g_Q1[BATCH * SEQ * DMODEL];
__device__ __align__(16) char g_K0[BATCH * SEQ * DMODEL];
__device__ __align__(16) char g_K1[BATCH * SEQ * DMODEL];
__device__ __align__(16) char g_Vt0[BATCH * DMODEL * SEQ];   // [b][d][s]
__device__ __align__(16) char g_Vt1[BATCH * DMODEL * SEQ];
__device__ __align__(16) char g_P0[BATCH * SEQ * SEQ];
__device__ __align__(16) char g_P1[BATCH * SEQ * SEQ];
__device__ __align__(16) float g_Qf[BATCH * SEQ * DMODEL];
__device__ __align__(16) float g_Kf[BATCH * SEQ * DMODEL];
__device__ __align__(16) float g_Vtf[BATCH * DMODEL * SEQ];
__device__ float g_sE[BATCH * SEQ];
__device__ float g_sW[3 * DMODEL];
__device__ float g_sQ[BATCH * SEQ];
__device__ float g_sK[BATCH * SEQ];
__device__ float g_sVt[BATCH * DMODEL];
__device__ float g_sP[BATCH * SEQ];
__device__ float g_mags[BATCH * SEQ];
__device__ float g_thresh;
__device__ unsigned int g_ctr[4];           // work-stealing counters

__device__ __forceinline__ uint32_t smem_u32(const void* p) {
    uint32_t a;
    asm("{ .reg .u64 t; cvta.to.shared.u64 t, %1; cvt.u32.u64 %0, t; }" : "=r"(a) : "l"(p));
    return a;
}
__device__ __forceinline__ void cp16(uint32_t dst, const void* src) {
    asm volatile("cp.async.cg.shared.global [%0], [%1], 16;" :: "r"(dst), "l"(src));
}
#define CP_COMMIT() asm volatile("cp.async.commit_group;" ::: "memory")
#define CP_WAIT1()  asm volatile("cp.async.wait_group 1;" ::: "memory")
#define CP_WAIT0()  asm volatile("cp.async.wait_group 0;" ::: "memory")

__device__ __forceinline__ void ldm4(uint32_t f[4], uint32_t addr) {
    asm volatile("ldmatrix.sync.aligned.m8n8.x4.shared.b16 {%0,%1,%2,%3}, [%4];"
        : "=r"(f[0]), "=r"(f[1]), "=r"(f[2]), "=r"(f[3]) : "r"(addr));
}
__device__ __forceinline__ void imma(int c[4], const uint32_t a[4],
                                     uint32_t b0, uint32_t b1) {
    asm volatile(
        "mma.sync.aligned.m16n8k32.row.col.s32.s8.s8.s32 "
        "{%0,%1,%2,%3}, {%4,%5,%6,%7}, {%8,%9}, {%0,%1,%2,%3};"
        : "+r"(c[0]), "+r"(c[1]), "+r"(c[2]), "+r"(c[3])
        : "r"(a[0]), "r"(a[1]), "r"(a[2]), "r"(a[3]), "r"(b0), "r"(b1));
}

__device__ __forceinline__ void quant2(float x, float inv, char& q0, char& q1) {
    float t = x * inv;
    int a = __float2int_rn(t);
    int b = __float2int_rn((t - (float)a) * 128.0f);
    q0 = (char)a;
    q1 = (char)b;
}

// ======================= quantize rows (+ optional L2 norm) =================
__global__ void quant_rows(const float* __restrict__ src, char* __restrict__ L0,
                           char* __restrict__ L1, float* __restrict__ scl, int C,
                           float* __restrict__ mags_out) {
    int row = blockIdx.x, tid = threadIdx.x;
    const float4* p = (const float4*)(src + (size_t)row * C);
    int n4 = C >> 2;
    float mx = 0.0f, sq = 0.0f;
    for (int i = tid; i < n4; i += 256) {
        float4 v = p[i];
        mx = fmaxf(mx, fmaxf(fmaxf(fabsf(v.x), fabsf(v.y)),
                             fmaxf(fabsf(v.z), fabsf(v.w))));
        sq += v.x * v.x + v.y * v.y + v.z * v.z + v.w * v.w;
    }
    __shared__ float sm[256];
    __shared__ float ss[256];
    sm[tid] = mx;
    ss[tid] = sq;
    __syncthreads();
    for (int off = 128; off > 0; off >>= 1) {
        if (tid < off) {
            sm[tid] = fmaxf(sm[tid], sm[tid + off]);
            ss[tid] += ss[tid + off];
        }
        __syncthreads();
    }
    float s = sm[0] * (1.0f / 127.0f);
    float inv = (s > 0.0f) ? 1.0f / s : 0.0f;
    if (tid == 0) {
        scl[row] = (s > 0.0f) ? s : 1.0f;
        if (mags_out) mags_out[row] = sqrtf(ss[0]);
    }
    char* l0 = L0 + (size_t)row * C;
    char* l1 = L1 + (size_t)row * C;
    for (int i = tid; i < n4; i += 256) {
        float4 v = p[i];
        char a0, a1, b0, b1, c0, c1, d0, d1;
        quant2(v.x, inv, a0, a1); quant2(v.y, inv, b0, b1);
        quant2(v.z, inv, c0, c1); quant2(v.w, inv, d0, d1);
        ((char4*)l0)[i] = make_char4(a0, b0, c0, d0);
        ((char4*)l1)[i] = make_char4(a1, b1, c1, d1);
    }
}

__global__ void thresh_kernel() {
    int tid = threadIdx.x;
    __shared__ double sd[256];
    double total = 0.0;
    for (int b = 0; b < BATCH; b++) {
        double local = 0.0;
        for (int i = tid; i < SEQ; i += 256) local += (double)g_mags[b * SEQ + i];
        sd[tid] = local;
        __syncthreads();
        for (int off = 128; off > 0; off >>= 1) {
            if (tid < off) sd[tid] += sd[tid + off];
            __syncthreads();
        }
        if (tid == 0) total += sd[0] * sd[0];
        __syncthreads();
    }
    if (tid == 0) g_thresh = (float)(total / ((double)BATCH * SEQ * SEQ));
}

// ======================= softmax (+ inline P quantization) ==================
__global__ void softmax_kernel(float* __restrict__ w) {
    size_t row = blockIdx.x;
    float4* p = (float4*)(w + row * SEQ);
    int tid = threadIdx.x;
    float4 v0 = p[tid];
    float4 v1 = p[tid + 256];
    float m = fmaxf(fmaxf(fmaxf(v0.x, v0.y), fmaxf(v0.z, v0.w)),
                    fmaxf(fmaxf(v1.x, v1.y), fmaxf(v1.z, v1.w)));
    __shared__ float sm[256];
    sm[tid] = m;
    __syncthreads();
    for (int off = 128; off > 0; off >>= 1) {
        if (tid < off) sm[tid] = fmaxf(sm[tid], sm[tid + off]);
        __syncthreads();
    }
    m = sm[0];
    __syncthreads();
    v0.x = expf(v0.x - m); v0.y = expf(v0.y - m);
    v0.z = expf(v0.z - m); v0.w = expf(v0.w - m);
    v1.x = expf(v1.x - m); v1.y = expf(v1.y - m);
    v1.z = expf(v1.z - m); v1.w = expf(v1.w - m);
    float s = v0.x + v0.y + v0.z + v0.w + v1.x + v1.y + v1.z + v1.w;
    sm[tid] = s;
    __syncthreads();
    for (int off = 128; off > 0; off >>= 1) {
        if (tid < off) sm[tid] += sm[tid + off];
        __syncthreads();
    }
    float inv = 1.0f / sm[0];
    if (tid == 0) g_sP[row] = inv * (1.0f / 127.0f);

    char q0[8], q1[8];
    quant2(v0.x * 127.0f, 1.0f, q0[0], q1[0]);
    quant2(v0.y * 127.0f, 1.0f, q0[1], q1[1]);
    quant2(v0.z * 127.0f, 1.0f, q0[2], q1[2]);
    quant2(v0.w * 127.0f, 1.0f, q0[3], q1[3]);
    quant2(v1.x * 127.0f, 1.0f, q0[4], q1[4]);
    quant2(v1.y * 127.0f, 1.0f, q0[5], q1[5]);
    quant2(v1.z * 127.0f, 1.0f, q0[6], q1[6]);
    quant2(v1.w * 127.0f, 1.0f, q0[7], q1[7]);
    ((char4*)(g_P0 + row * SEQ))[tid] = make_char4(q0[0], q0[1], q0[2], q0[3]);
    ((char4*)(g_P1 + row * SEQ))[tid] = make_char4(q1[0], q1[1], q1[2], q1[3]);
    ((char4*)(g_P0 + row * SEQ))[tid + 256] = make_char4(q0[4], q0[5], q0[6], q0[7]);
    ((char4*)(g_P1 + row * SEQ))[tid + 256] = make_char4(q1[4], q1[5], q1[6], q1[7]);

    v0.x *= inv; v0.y *= inv; v0.z *= inv; v0.w *= inv;
    v1.x *= inv; v1.y *= inv; v1.z *= inv; v1.w *= inv;
    p[tid] = v0;
    p[tid + 256] = v1;
}

// ======================= pipelined IMMA GEMM core ===========================
// C[128x128]/CTA, 16 warps (4x4) each 32x32, BK=128 int8, 3-stage ring.
__device__ __forceinline__ void load_stage(
    uint32_t sb, int slot, int row, int qs,
    const char* __restrict__ A0, const char* __restrict__ A1,
    const char* __restrict__ B0, const char* __restrict__ B1,
    int lda, int ldb, int m0, int n0, int k0)
{
    uint32_t drow = sb + (uint32_t)slot * STAGE_BYTES + (uint32_t)row * 128;
    const char* a0 = A0 + (size_t)(m0 + row) * lda + k0;
    const char* a1 = A1 + (size_t)(m0 + row) * lda + k0;
    const char* b0 = B0 + (size_t)(n0 + row) * ldb + k0;
    const char* b1 = B1 + (size_t)(n0 + row) * ldb + k0;
    #pragma unroll
    for (int i = 0; i < 2; i++) {
        int seg = qs * 2 + i;
        uint32_t sw = (uint32_t)((seg ^ (row & 7)) * 16);
        cp16(drow + sw,                   a0 + seg * 16);
        cp16(drow + sw + PLANE_BYTES,     a1 + seg * 16);
        cp16(drow + sw + 2 * PLANE_BYTES, b0 + seg * 16);
        cp16(drow + sw + 3 * PLANE_BYTES, b1 + seg * 16);
    }
}

__device__ __forceinline__ void gemm_run(
    const char* __restrict__ A0, const char* __restrict__ A1,
    const char* __restrict__ B0, const char* __restrict__ B1,
    int lda, int ldb, int K, int m0, int n0,
    int acc0[2][4][4], int accX[2][4][4])
{
    extern __shared__ __align__(16) char smem[];
    uint32_t sb = smem_u32(smem);
    int tid = threadIdx.x, lane = tid & 31, warp = tid >> 5;
    int wm = (warp >> 2) * 32, wn = (warp & 3) * 32;
    int row = tid >> 2, qs = tid & 3;
    int g = lane >> 3, r = lane & 7;
    int rb = (g & 1) * 8 + r, hsel = g >> 1;

    int NC = K >> 7;   // BK=128 int8
    #pragma unroll
    for (int s = 0; s < NSTAGE - 1; s++) {
        load_stage(sb, s, row, qs, A0, A1, B0, B1, lda, ldb, m0, n0, s * 128);
        CP_COMMIT();
    }

    uint32_t arow = (uint32_t)((wm + rb) * 128);
    uint32_t brow = (uint32_t)((wn + rb) * 128);

    for (int c = 0; c < NC; c++) {
        if (c == NC - 1) CP_WAIT0(); else CP_WAIT1();   // final chunk must be fully arrived
        __syncthreads();
        if (c + 2 < NC) {
            load_stage(sb, (c + 2) % NSTAGE, row, qs, A0, A1, B0, B1,
                       lda, ldb, m0, n0, (c + 2) * 128);
            CP_COMMIT();
        }
        uint32_t st = sb + (uint32_t)(c % NSTAGE) * STAGE_BYTES;
        #pragma unroll
        for (int kb = 0; kb < 4; kb++) {
            uint32_t segoff = (uint32_t)((((kb * 2) | hsel) ^ r) * 16);
            uint32_t a0f[2][4], a1f[2][4], b0f[2][4], b1f[2][4];
            #pragma unroll
            for (int mi = 0; mi < 2; mi++) {
                uint32_t ad = st + arow + (uint32_t)(mi * 16 * 128) + segoff;
                ldm4(a0f[mi], ad);
                ldm4(a1f[mi], ad + PLANE_BYTES);
            }
            #pragma unroll
            for (int nb = 0; nb < 2; nb++) {
                uint32_t bd = st + 2 * PLANE_BYTES + brow + (uint32_t)(nb * 16 * 128) + segoff;
                ldm4(b0f[nb], bd);
                ldm4(b1f[nb], bd + PLANE_BYTES);
            }
            #pragma unroll
            for (int mi = 0; mi < 2; mi++)
                #pragma unroll
                for (int nb = 0; nb < 2; nb++)
                    #pragma unroll
                    for (int s = 0; s < 2; s++) {
                        int ni = nb * 2 + s;
                        imma(acc0[mi][ni], a0f[mi], b0f[nb][s], b0f[nb][s + 2]);
                        imma(accX[mi][ni], a0f[mi], b1f[nb][s], b1f[nb][s + 2]);
                        imma(accX[mi][ni], a1f[mi], b0f[nb][s], b0f[nb][s + 2]);
                    }
        }
    }
}

#define COMBINE(mi, ni, j) ((float)acc0[mi][ni][j] + (float)accX[mi][ni][j] * 0.0078125f)

// ======================= persistent GEMM kernels ============================
__global__ void __launch_bounds__(NTHREADS, 1) qkv_tc() {
    __shared__ int s_tile;
    for (;;) {
        __syncthreads();
        if (threadIdx.x == 0) s_tile = (int)atomicAdd(&g_ctr[0], 1u);
        __syncthreads();
        int t = s_tile;
        if (t >= 1536) return;
        int n0 = (t & 7) * 128;
        int rest = t >> 3;
        int m0 = (rest & 63) * 128;
        int z = rest >> 6;

        const char* Bw0 = g_W0 + (size_t)z * DMODEL * DMODEL;
        const char* Bw1 = g_W1 + (size_t)z * DMODEL * DMODEL;
        int acc0[2][4][4] = {}, accX[2][4][4] = {};
        gemm_run(g_E0, g_E1, Bw0, Bw1, DMODEL, DMODEL, DMODEL, m0, n0, acc0, accX);

        int lane = threadIdx.x & 31, warp = threadIdx.x >> 5;
        int wm = (warp >> 2) * 32, wn = (warp & 3) * 32;
        #pragma unroll
        for (int mi = 0; mi < 2; mi++)
            #pragma unroll
            for (int h = 0; h < 2; h++) {
                int rg = m0 + wm + mi * 16 + h * 8 + (lane >> 2);
                float sa = g_sE[rg];
                #pragma unroll
                for (int ni = 0; ni < 4; ni++) {
                    int col = n0 + wn + ni * 8 + (lane & 3) * 2;
                    float sb0 = g_sW[z * DMODEL + col];
                    float sb1 = g_sW[z * DMODEL + col + 1];
                    float x0 = sa * sb0 * COMBINE(mi, ni, h * 2);
                    float x1 = sa * sb1 * COMBINE(mi, ni, h * 2 + 1);
                    if (z == 2) {
                        int b = rg >> 11, s = rg & (SEQ - 1);
                        float* vb = g_Vtf + (size_t)b * DMODEL * SEQ;
                        vb[(size_t)col * SEQ + s] = x0;
                        vb[(size_t)(col + 1) * SEQ + s] = x1;
                    } else {
                        float* C = (z == 0) ? g_Qf : g_Kf;
                        *(float2*)&C[(size_t)rg * DMODEL + col] = make_float2(x0, x1);
                    }
                }
            }
    }
}

__global__ void __launch_bounds__(NTHREADS, 1) scores_tc(
    const float* __restrict__ intent_bias, const int* __restrict__ mask,
    float* __restrict__ wts)
{
    __shared__ int s_tile;
    for (;;) {
        __syncthreads();
        if (threadIdx.x == 0) s_tile = (int)atomicAdd(&g_ctr[1], 1u);
        __syncthreads();
        int t = s_tile;
        if (t >= 1024) return;
        int n0 = (t & 15) * 128;
        int m0 = ((t >> 4) & 15) * 128;
        int b = t >> 8;

        size_t off = (size_t)b * SEQ * DMODEL;
        int acc0[2][4][4] = {}, accX[2][4][4] = {};
        gemm_run(g_Q0 + off, g_Q1 + off, g_K0 + off, g_K1 + off,
                 DMODEL, DMODEL, DMODEL, m0, n0, acc0, accX);

        int lane = threadIdx.x & 31, warp = threadIdx.x >> 5;
        int wm = (warp >> 2) * 32, wn = (warp & 3) * 32;
        float th = g_thresh;
        float bias = intent_bias[0];
        #pragma unroll
        for (int mi = 0; mi < 2; mi++)
            #pragma unroll
            for (int h = 0; h < 2; h++) {
                int q = m0 + wm + mi * 16 + h * 8 + (lane >> 2);
                float mq = g_mags[b * SEQ + q];
                float sa = g_sQ[b * SEQ + q] * 0.03125f;
                size_t rb2 = ((size_t)b * SEQ + q) * SEQ;
                #pragma unroll
                for (int ni = 0; ni < 4; ni++) {
                    int col = n0 + wn + ni * 8 + (lane & 3) * 2;
                    float x0 = sa * g_sK[b * SEQ + col] * COMBINE(mi, ni, h * 2);
                    float x1 = sa * g_sK[b * SEQ + col + 1] * COMBINE(mi, ni, h * 2 + 1);
                    float mk0 = g_mags[b * SEQ + col];
                    float mk1 = g_mags[b * SEQ + col + 1];
                    if (mq * mk0 > th) x0 += bias;
                    if (mq * mk1 > th) x1 += bias;
                    int2 mv = *(const int2*)&mask[rb2 + col];
                    if (mv.x == 0) x0 = -1e9f;
                    if (mv.y == 0) x1 = -1e9f;
                    *(float2*)&wts[rb2 + col] = make_float2(x0, x1);
                }
            }
    }
}

__global__ void __launch_bounds__(NTHREADS, 1) av_tc(float* __restrict__ att) {
    __shared__ int s_tile;
    for (;;) {
        __syncthreads();
        if (threadIdx.x == 0) s_tile = (int)atomicAdd(&g_ctr[2], 1u);
        __syncthreads();
        int t = s_tile;
        if (t >= 512) return;
        int n0 = (t & 7) * 128;
        int m0 = ((t >> 3) & 15) * 128;
        int b = t >> 7;

        size_t po = (size_t)b * SEQ * SEQ;
        size_t vo = (size_t)b * DMODEL * SEQ;
        int acc0[2][4][4] = {}, accX[2][4][4] = {};
        gemm_run(g_P0 + po, g_P1 + po, g_Vt0 + vo, g_Vt1 + vo,
                 SEQ, SEQ, SEQ, m0, n0, acc0, accX);

        int lane = threadIdx.x & 31, warp = threadIdx.x >> 5;
        int wm = (warp >> 2) * 32, wn = (warp & 3) * 32;
        #pragma unroll
        for (int mi = 0; mi < 2; mi++)
            #pragma unroll
            for (int h = 0; h < 2; h++) {
                int s = m0 + wm + mi * 16 + h * 8 + (lane >> 2);
                float sa = g_sP[b * SEQ + s];
                #pragma unroll
                for (int ni = 0; ni < 4; ni++) {
                    int col = n0 + wn + ni * 8 + (lane & 3) * 2;
                    float x0 = sa * g_sVt[b * DMODEL + col] * COMBINE(mi, ni, h * 2);
                    float x1 = sa * g_sVt[b * DMODEL + col + 1] * COMBINE(mi, ni, h * 2 + 1);
                    *(float2*)&att[((size_t)b * SEQ + s) * DMODEL + col] =
                        make_float2(x0, x1);
                }
            }
    }
}

// ======================= launch =============================================
extern "C" void kernel_launch(void* const* d_in, const int* in_sizes, int n_in,
                              void* d_out, int out_size)
{
    (void)in_sizes; (void)n_in; (void)out_size;
    const float* E    = (const float*)d_in[0];
    const float* Wq   = (const float*)d_in[1];
    const float* Wk   = (const float*)d_in[2];
    const float* Wv   = (const float*)d_in[3];
    const float* bias = (const float*)d_in[4];
    const int*   mask = (const int*)d_in[5];

    float* out = (float*)d_out;
    float* att = out;                                  // [B,S,D]
    float* wts = out + (size_t)BATCH * SEQ * DMODEL;   // [B,S,S]

    cudaFuncSetAttribute(qkv_tc,    cudaFuncAttributeMaxDynamicSharedMemorySize, SMEM_TOTAL);
    cudaFuncSetAttribute(scores_tc, cudaFuncAttributeMaxDynamicSharedMemorySize, SMEM_TOTAL);
    cudaFuncSetAttribute(av_tc,     cudaFuncAttributeMaxDynamicSharedMemorySize, SMEM_TOTAL);

    char *E0, *E1, *W0, *W1, *Q0, *Q1, *K0, *K1, *V0, *V1;
    float *sE, *sW, *sQ, *sK, *sV, *Qf, *Kf, *Vf, *mg;
    unsigned int* ctr;
    cudaGetSymbolAddress((void**)&E0, g_E0); cudaGetSymbolAddress((void**)&E1, g_E1);
    cudaGetSymbolAddress((void**)&W0, g_W0); cudaGetSymbolAddress((void**)&W1, g_W1);
    cudaGetSymbolAddress((void**)&Q0, g_Q0); cudaGetSymbolAddress((void**)&Q1, g_Q1);
    cudaGetSymbolAddress((void**)&K0, g_K0); cudaGetSymbolAddress((void**)&K1, g_K1);
    cudaGetSymbolAddress((void**)&V0, g_Vt0); cudaGetSymbolAddress((void**)&V1, g_Vt1);
    cudaGetSymbolAddress((void**)&sE, g_sE); cudaGetSymbolAddress((void**)&sW, g_sW);
    cudaGetSymbolAddress((void**)&sQ, g_sQ); cudaGetSymbolAddress((void**)&sK, g_sK);
    cudaGetSymbolAddress((void**)&sV, g_sVt);
    cudaGetSymbolAddress((void**)&Qf, g_Qf); cudaGetSymbolAddress((void**)&Kf, g_Kf);
    cudaGetSymbolAddress((void**)&Vf, g_Vtf);
    cudaGetSymbolAddress((void**)&mg, g_mags);
    cudaGetSymbolAddress((void**)&ctr, g_ctr);

    cudaMemsetAsync(ctr, 0, 4 * sizeof(unsigned int));

    quant_rows<<<BATCH * SEQ, 256>>>(E, E0, E1, sE, DMODEL, mg);   // mags fused
    quant_rows<<<DMODEL, 256>>>(Wq, W0, W1, sW, DMODEL, nullptr);
    quant_rows<<<DMODEL, 256>>>(Wk, W0 + (size_t)DMODEL * DMODEL,
                                W1 + (size_t)DMODEL * DMODEL, sW + DMODEL, DMODEL, nullptr);
    quant_rows<<<DMODEL, 256>>>(Wv, W0 + 2 * (size_t)DMODEL * DMODEL,
                                W1 + 2 * (size_t)DMODEL * DMODEL, sW + 2 * DMODEL, DMODEL, nullptr);

    thresh_kernel<<<1, 256>>>();

    qkv_tc<<<PGRID, NTHREADS, SMEM_TOTAL>>>();

    quant_rows<<<BATCH * SEQ, 256>>>(Qf, Q0, Q1, sQ, DMODEL, nullptr);
    quant_rows<<<BATCH * SEQ, 256>>>(Kf, K0, K1, sK, DMODEL, nullptr);
    quant_rows<<<BATCH * DMODEL, 256>>>(Vf, V0, V1, sV, SEQ, nullptr);

    scores_tc<<<PGRID, NTHREADS, SMEM_TOTAL>>>(bias, mask, wts);

    softmax_kernel<<<BATCH * SEQ, 256>>>(wts);

    av_tc<<<PGRID, NTHREADS, SMEM_TOTAL>>>(att);
}

// round 15
// speedup vs baseline: 1.1910x; 1.0585x over previous
#include <cuda_runtime.h>
#include <cuda_bf16.h>
#include <cstdint>
#include <math.h>

#define BATCH 4
#define SEQ   2048
#define DMODEL 1024

// smem: BK=128 int8 -> 128B rows; planes A0|A1|B0|B1 16KB each; 3 stages
#define PLANE_BYTES  16384
#define STAGE_BYTES  (4 * PLANE_BYTES)      // 64KB
#define NSTAGE       3
#define SMEM_TOTAL   (NSTAGE * STAGE_BYTES) // 192KB
#define NTHREADS     512

// ======================= scratch ============================================
__device__ __align__(16) char g_E0[BATCH * SEQ * DMODEL];
__device__ __align__(16) char g_E1[BATCH * SEQ * DMODEL];
__device__ __align__(16) char g_W0[3 * DMODEL * DMODEL];
__device__ __align__(16) char g_W1[3 * DMODEL * DMODEL];
__device__ __align__(16) char g_Q0[BATCH * SEQ * DMODEL];
__device__ __align__(16) char g_Q1[BATCH * SEQ * DMODEL];
__device__ __align__(16) char g_K0[BATCH * SEQ * DMODEL];
__device__ __align__(16) char g_K1[BATCH * SEQ * DMODEL];
__device__ __align__(16) char g_Vt0[BATCH * DMODEL * SEQ];   // [b][d][s]
__device__ __align__(16) char g_Vt1[BATCH * DMODEL * SEQ];
__device__ __align__(16) char g_P0[BATCH * SEQ * SEQ];
__device__ __align__(16) char g_P1[BATCH * SEQ * SEQ];
__device__ __align__(16) float g_Qf[BATCH * SEQ * DMODEL];
__device__ __align__(16) float g_Kf[BATCH * SEQ * DMODEL];
__device__ __align__(16) float g_Vtf[BATCH * DMODEL * SEQ];
__device__ float g_sE[BATCH * SEQ];
__device__ float g_sW[3 * DMODEL];
__device__ float g_sQ[BATCH * SEQ];
__device__ float g_sK[BATCH * SEQ];
__device__ float g_sVt[BATCH * DMODEL];
__device__ float g_sP[BATCH * SEQ];
__device__ float g_mags[BATCH * SEQ];
__device__ float g_thresh;

__device__ __forceinline__ uint32_t smem_u32(const void* p) {
    uint32_t a;
    asm("{ .reg .u64 t; cvta.to.shared.u64 t, %1; cvt.u32.u64 %0, t; }" : "=r"(a) : "l"(p));
    return a;
}
__device__ __forceinline__ void cp16(uint32_t dst, const void* src) {
    asm volatile("cp.async.cg.shared.global [%0], [%1], 16;" :: "r"(dst), "l"(src));
}
#define CP_COMMIT() asm volatile("cp.async.commit_group;" ::: "memory")
#define CP_WAIT1()  asm volatile("cp.async.wait_group 1;" ::: "memory")
#define CP_WAIT0()  asm volatile("cp.async.wait_group 0;" ::: "memory")

__device__ __forceinline__ void ldm4(uint32_t f[4], uint32_t addr) {
    asm volatile("ldmatrix.sync.aligned.m8n8.x4.shared.b16 {%0,%1,%2,%3}, [%4];"
        : "=r"(f[0]), "=r"(f[1]), "=r"(f[2]), "=r"(f[3]) : "r"(addr));
}
__device__ __forceinline__ void imma(int c[4], const uint32_t a[4],
                                     uint32_t b0, uint32_t b1) {
    asm volatile(
        "mma.sync.aligned.m16n8k32.row.col.s32.s8.s8.s32 "
        "{%0,%1,%2,%3}, {%4,%5,%6,%7}, {%8,%9}, {%0,%1,%2,%3};"
        : "+r"(c[0]), "+r"(c[1]), "+r"(c[2]), "+r"(c[3])
        : "r"(a[0]), "r"(a[1]), "r"(a[2]), "r"(a[3]), "r"(b0), "r"(b1));
}

__device__ __forceinline__ void quant2(float x, float inv, char& q0, char& q1) {
    float t = x * inv;
    int a = __float2int_rn(t);
    int b = __float2int_rn((t - (float)a) * 128.0f);
    q0 = (char)a;
    q1 = (char)b;
}

// ======================= quantize rows (+ optional fused L2 norm) ===========
__global__ void quant_rows(const float* __restrict__ src, char* __restrict__ L0,
                           char* __restrict__ L1, float* __restrict__ scl, int C,
                           float* __restrict__ mags_out) {
    int row = blockIdx.x, tid = threadIdx.x;
    const float4* p = (const float4*)(src + (size_t)row * C);
    int n4 = C >> 2;
    float mx = 0.0f, sq = 0.0f;
    for (int i = tid; i < n4; i += 256) {
        float4 v = p[i];
        mx = fmaxf(mx, fmaxf(fmaxf(fabsf(v.x), fabsf(v.y)),
                             fmaxf(fabsf(v.z), fabsf(v.w))));
        if (mags_out) sq += v.x * v.x + v.y * v.y + v.z * v.z + v.w * v.w;
    }
    __shared__ float sm[256];
    __shared__ float ss[256];
    sm[tid] = mx;
    ss[tid] = sq;
    __syncthreads();
    for (int off = 128; off > 0; off >>= 1) {
        if (tid < off) {
            sm[tid] = fmaxf(sm[tid], sm[tid + off]);
            ss[tid] += ss[tid + off];
        }
        __syncthreads();
    }
    float s = sm[0] * (1.0f / 127.0f);
    float inv = (s > 0.0f) ? 1.0f / s : 0.0f;
    if (tid == 0) {
        scl[row] = (s > 0.0f) ? s : 1.0f;
        if (mags_out) mags_out[row] = sqrtf(ss[0]);
    }
    char* l0 = L0 + (size_t)row * C;
    char* l1 = L1 + (size_t)row * C;
    for (int i = tid; i < n4; i += 256) {
        float4 v = p[i];
        char a0, a1, b0, b1, c0, c1, d0, d1;
        quant2(v.x, inv, a0, a1); quant2(v.y, inv, b0, b1);
        quant2(v.z, inv, c0, c1); quant2(v.w, inv, d0, d1);
        ((char4*)l0)[i] = make_char4(a0, b0, c0, d0);
        ((char4*)l1)[i] = make_char4(a1, b1, c1, d1);
    }
}

__global__ void thresh_kernel() {
    int tid = threadIdx.x;
    __shared__ double sd[256];
    double total = 0.0;
    for (int b = 0; b < BATCH; b++) {
        double local = 0.0;
        for (int i = tid; i < SEQ; i += 256) local += (double)g_mags[b * SEQ + i];
        sd[tid] = local;
        __syncthreads();
        for (int off = 128; off > 0; off >>= 1) {
            if (tid < off) sd[tid] += sd[tid + off];
            __syncthreads();
        }
        if (tid == 0) total += sd[0] * sd[0];
        __syncthreads();
    }
    if (tid == 0) g_thresh = (float)(total / ((double)BATCH * SEQ * SEQ));
}

// ======================= softmax (+ inline P quantization) ==================
__global__ void softmax_kernel(float* __restrict__ w) {
    size_t row = blockIdx.x;
    float4* p = (float4*)(w + row * SEQ);
    int tid = threadIdx.x;
    float4 v0 = p[tid];
    float4 v1 = p[tid + 256];
    float m = fmaxf(fmaxf(fmaxf(v0.x, v0.y), fmaxf(v0.z, v0.w)),
                    fmaxf(fmaxf(v1.x, v1.y), fmaxf(v1.z, v1.w)));
    __shared__ float sm[256];
    sm[tid] = m;
    __syncthreads();
    for (int off = 128; off > 0; off >>= 1) {
        if (tid < off) sm[tid] = fmaxf(sm[tid], sm[tid + off]);
        __syncthreads();
    }
    m = sm[0];
    __syncthreads();
    v0.x = expf(v0.x - m); v0.y = expf(v0.y - m);
    v0.z = expf(v0.z - m); v0.w = expf(v0.w - m);
    v1.x = expf(v1.x - m); v1.y = expf(v1.y - m);
    v1.z = expf(v1.z - m); v1.w = expf(v1.w - m);
    float s = v0.x + v0.y + v0.z + v0.w + v1.x + v1.y + v1.z + v1.w;
    sm[tid] = s;
    __syncthreads();
    for (int off = 128; off > 0; off >>= 1) {
        if (tid < off) sm[tid] += sm[tid + off];
        __syncthreads();
    }
    float inv = 1.0f / sm[0];
    if (tid == 0) g_sP[row] = inv * (1.0f / 127.0f);

    char q0[8], q1[8];
    quant2(v0.x * 127.0f, 1.0f, q0[0], q1[0]);
    quant2(v0.y * 127.0f, 1.0f, q0[1], q1[1]);
    quant2(v0.z * 127.0f, 1.0f, q0[2], q1[2]);
    quant2(v0.w * 127.0f, 1.0f, q0[3], q1[3]);
    quant2(v1.x * 127.0f, 1.0f, q0[4], q1[4]);
    quant2(v1.y * 127.0f, 1.0f, q0[5], q1[5]);
    quant2(v1.z * 127.0f, 1.0f, q0[6], q1[6]);
    quant2(v1.w * 127.0f, 1.0f, q0[7], q1[7]);
    ((char4*)(g_P0 + row * SEQ))[tid] = make_char4(q0[0], q0[1], q0[2], q0[3]);
    ((char4*)(g_P1 + row * SEQ))[tid] = make_char4(q1[0], q1[1], q1[2], q1[3]);
    ((char4*)(g_P0 + row * SEQ))[tid + 256] = make_char4(q0[4], q0[5], q0[6], q0[7]);
    ((char4*)(g_P1 + row * SEQ))[tid + 256] = make_char4(q1[4], q1[5], q1[6], q1[7]);

    v0.x *= inv; v0.y *= inv; v0.z *= inv; v0.w *= inv;
    v1.x *= inv; v1.y *= inv; v1.z *= inv; v1.w *= inv;
    p[tid] = v0;
    p[tid + 256] = v1;
}

// ======================= pipelined IMMA GEMM core ===========================
// C[128x128]/CTA, 16 warps (4x4) each 32x32, BK=128 int8, 3-stage ring.
__device__ __forceinline__ void load_stage(
    uint32_t sb, int slot, int row, int qs,
    const char* __restrict__ A0, const char* __restrict__ A1,
    const char* __restrict__ B0, const char* __restrict__ B1,
    int lda, int ldb, int m0, int n0, int k0)
{
    uint32_t drow = sb + (uint32_t)slot * STAGE_BYTES + (uint32_t)row * 128;
    const char* a0 = A0 + (size_t)(m0 + row) * lda + k0;
    const char* a1 = A1 + (size_t)(m0 + row) * lda + k0;
    const char* b0 = B0 + (size_t)(n0 + row) * ldb + k0;
    const char* b1 = B1 + (size_t)(n0 + row) * ldb + k0;
    #pragma unroll
    for (int i = 0; i < 2; i++) {
        int seg = qs * 2 + i;
        uint32_t sw = (uint32_t)((seg ^ (row & 7)) * 16);
        cp16(drow + sw,                   a0 + seg * 16);
        cp16(drow + sw + PLANE_BYTES,     a1 + seg * 16);
        cp16(drow + sw + 2 * PLANE_BYTES, b0 + seg * 16);
        cp16(drow + sw + 3 * PLANE_BYTES, b1 + seg * 16);
    }
}

__device__ __forceinline__ void gemm_run(
    const char* __restrict__ A0, const char* __restrict__ A1,
    const char* __restrict__ B0, const char* __restrict__ B1,
    int lda, int ldb, int K, int m0, int n0,
    int acc0[2][4][4], int accX[2][4][4])
{
    extern __shared__ __align__(16) char smem[];
    uint32_t sb = smem_u32(smem);
    int tid = threadIdx.x, lane = tid & 31, warp = tid >> 5;
    int wm = (warp >> 2) * 32, wn = (warp & 3) * 32;
    int row = tid >> 2, qs = tid & 3;
    int g = lane >> 3, r = lane & 7;
    int rb = (g & 1) * 8 + r, hsel = g >> 1;

    int NC = K >> 7;   // BK=128 int8
    #pragma unroll
    for (int s = 0; s < NSTAGE - 1; s++) {
        load_stage(sb, s, row, qs, A0, A1, B0, B1, lda, ldb, m0, n0, s * 128);
        CP_COMMIT();
    }

    uint32_t arow = (uint32_t)((wm + rb) * 128);
    uint32_t brow = (uint32_t)((wn + rb) * 128);

    for (int c = 0; c < NC; c++) {
        if (c == NC - 1) CP_WAIT0(); else CP_WAIT1();   // last chunk must be fully resident
        __syncthreads();
        if (c + 2 < NC) {
            load_stage(sb, (c + 2) % NSTAGE, row, qs, A0, A1, B0, B1,
                       lda, ldb, m0, n0, (c + 2) * 128);
            CP_COMMIT();
        }
        uint32_t st = sb + (uint32_t)(c % NSTAGE) * STAGE_BYTES;
        #pragma unroll
        for (int kb = 0; kb < 4; kb++) {
            uint32_t segoff = (uint32_t)((((kb * 2) | hsel) ^ r) * 16);
            uint32_t a0f[2][4], a1f[2][4], b0f[2][4], b1f[2][4];
            #pragma unroll
            for (int mi = 0; mi < 2; mi++) {
                uint32_t ad = st + arow + (uint32_t)(mi * 16 * 128) + segoff;
                ldm4(a0f[mi], ad);
                ldm4(a1f[mi], ad + PLANE_BYTES);
            }
            #pragma unroll
            for (int nb = 0; nb < 2; nb++) {
                uint32_t bd = st + 2 * PLANE_BYTES + brow + (uint32_t)(nb * 16 * 128) + segoff;
                ldm4(b0f[nb], bd);
                ldm4(b1f[nb], bd + PLANE_BYTES);
            }
            #pragma unroll
            for (int mi = 0; mi < 2; mi++)
                #pragma unroll
                for (int nb = 0; nb < 2; nb++)
                    #pragma unroll
                    for (int s = 0; s < 2; s++) {
                        int ni = nb * 2 + s;
                        imma(acc0[mi][ni], a0f[mi], b0f[nb][s], b0f[nb][s + 2]);
                        imma(accX[mi][ni], a0f[mi], b1f[nb][s], b1f[nb][s + 2]);
                        imma(accX[mi][ni], a1f[mi], b0f[nb][s], b0f[nb][s + 2]);
                    }
        }
    }
}

#define COMBINE(mi, ni, j) ((float)acc0[mi][ni][j] + (float)accX[mi][ni][j] * 0.0078125f)

// ======================= GEMM kernels =======================================
__global__ void __launch_bounds__(NTHREADS, 1) qkv_tc() {
    int z = blockIdx.z;
    const char* Bw0 = g_W0 + (size_t)z * DMODEL * DMODEL;
    const char* Bw1 = g_W1 + (size_t)z * DMODEL * DMODEL;
    int m0 = blockIdx.y * 128, n0 = blockIdx.x * 128;
    int acc0[2][4][4] = {}, accX[2][4][4] = {};
    gemm_run(g_E0, g_E1, Bw0, Bw1, DMODEL, DMODEL, DMODEL, m0, n0, acc0, accX);

    int lane = threadIdx.x & 31, warp = threadIdx.x >> 5;
    int wm = (warp >> 2) * 32, wn = (warp & 3) * 32;
    #pragma unroll
    for (int mi = 0; mi < 2; mi++)
        #pragma unroll
        for (int h = 0; h < 2; h++) {
            int rg = m0 + wm + mi * 16 + h * 8 + (lane >> 2);
            float sa = g_sE[rg];
            #pragma unroll
            for (int ni = 0; ni < 4; ni++) {
                int col = n0 + wn + ni * 8 + (lane & 3) * 2;
                float sb0 = g_sW[z * DMODEL + col];
                float sb1 = g_sW[z * DMODEL + col + 1];
                float x0 = sa * sb0 * COMBINE(mi, ni, h * 2);
                float x1 = sa * sb1 * COMBINE(mi, ni, h * 2 + 1);
                if (z == 2) {
                    int b = rg >> 11, s = rg & (SEQ - 1);
                    float* vb = g_Vtf + (size_t)b * DMODEL * SEQ;
                    vb[(size_t)col * SEQ + s] = x0;
                    vb[(size_t)(col + 1) * SEQ + s] = x1;
                } else {
                    float* C = (z == 0) ? g_Qf : g_Kf;
                    *(float2*)&C[(size_t)rg * DMODEL + col] = make_float2(x0, x1);
                }
            }
        }
}

__global__ void __launch_bounds__(NTHREADS, 1) scores_tc(
    const float* __restrict__ intent_bias, const int* __restrict__ mask,
    float* __restrict__ wts)
{
    int b = blockIdx.z;
    size_t off = (size_t)b * SEQ * DMODEL;
    int m0 = blockIdx.y * 128, n0 = blockIdx.x * 128;
    int acc0[2][4][4] = {}, accX[2][4][4] = {};
    gemm_run(g_Q0 + off, g_Q1 + off, g_K0 + off, g_K1 + off,
             DMODEL, DMODEL, DMODEL, m0, n0, acc0, accX);

    int lane = threadIdx.x & 31, warp = threadIdx.x >> 5;
    int wm = (warp >> 2) * 32, wn = (warp & 3) * 32;
    float th = g_thresh;
    float bias = intent_bias[0];
    #pragma unroll
    for (int mi = 0; mi < 2; mi++)
        #pragma unroll
        for (int h = 0; h < 2; h++) {
            int q = m0 + wm + mi * 16 + h * 8 + (lane >> 2);
            float mq = g_mags[b * SEQ + q];
            float sa = g_sQ[b * SEQ + q] * 0.03125f;
            size_t rb2 = ((size_t)b * SEQ + q) * SEQ;
            #pragma unroll
            for (int ni = 0; ni < 4; ni++) {
                int col = n0 + wn + ni * 8 + (lane & 3) * 2;
                float x0 = sa * g_sK[b * SEQ + col] * COMBINE(mi, ni, h * 2);
                float x1 = sa * g_sK[b * SEQ + col + 1] * COMBINE(mi, ni, h * 2 + 1);
                float mk0 = g_mags[b * SEQ + col];
                float mk1 = g_mags[b * SEQ + col + 1];
                if (mq * mk0 > th) x0 += bias;
                if (mq * mk1 > th) x1 += bias;
                int2 mv = *(const int2*)&mask[rb2 + col];
                if (mv.x == 0) x0 = -1e9f;
                if (mv.y == 0) x1 = -1e9f;
                *(float2*)&wts[rb2 + col] = make_float2(x0, x1);
            }
        }
}

__global__ void __launch_bounds__(NTHREADS, 1) av_tc(float* __restrict__ att) {
    int b = blockIdx.z;
    size_t po = (size_t)b * SEQ * SEQ;
    size_t vo = (size_t)b * DMODEL * SEQ;
    int m0 = blockIdx.y * 128, n0 = blockIdx.x * 128;
    int acc0[2][4][4] = {}, accX[2][4][4] = {};
    gemm_run(g_P0 + po, g_P1 + po, g_Vt0 + vo, g_Vt1 + vo,
             SEQ, SEQ, SEQ, m0, n0, acc0, accX);

    int lane = threadIdx.x & 31, warp = threadIdx.x >> 5;
    int wm = (warp >> 2) * 32, wn = (warp & 3) * 32;
    #pragma unroll
    for (int mi = 0; mi < 2; mi++)
        #pragma unroll
        for (int h = 0; h < 2; h++) {
            int s = m0 + wm + mi * 16 + h * 8 + (lane >> 2);
            float sa = g_sP[b * SEQ + s];
            #pragma unroll
            for (int ni = 0; ni < 4; ni++) {
                int col = n0 + wn + ni * 8 + (lane & 3) * 2;
                float x0 = sa * g_sVt[b * DMODEL + col] * COMBINE(mi, ni, h * 2);
                float x1 = sa * g_sVt[b * DMODEL + col + 1] * COMBINE(mi, ni, h * 2 + 1);
                *(float2*)&att[((size_t)b * SEQ + s) * DMODEL + col] =
                    make_float2(x0, x1);
            }
        }
}

// ======================= launch =============================================
extern "C" void kernel_launch(void* const* d_in, const int* in_sizes, int n_in,
                              void* d_out, int out_size)
{
    (void)in_sizes; (void)n_in; (void)out_size;
    const float* E    = (const float*)d_in[0];
    const float* Wq   = (const float*)d_in[1];
    const float* Wk   = (const float*)d_in[2];
    const float* Wv   = (const float*)d_in[3];
    const float* bias = (const float*)d_in[4];
    const int*   mask = (const int*)d_in[5];

    float* out = (float*)d_out;
    float* att = out;                                  // [B,S,D]
    float* wts = out + (size_t)BATCH * SEQ * DMODEL;   // [B,S,S]

    cudaFuncSetAttribute(qkv_tc,    cudaFuncAttributeMaxDynamicSharedMemorySize, SMEM_TOTAL);
    cudaFuncSetAttribute(scores_tc, cudaFuncAttributeMaxDynamicSharedMemorySize, SMEM_TOTAL);
    cudaFuncSetAttribute(av_tc,     cudaFuncAttributeMaxDynamicSharedMemorySize, SMEM_TOTAL);

    char *E0, *E1, *W0, *W1, *Q0, *Q1, *K0, *K1, *V0, *V1;
    float *sE, *sW, *sQ, *sK, *sV, *Qf, *Kf, *Vf, *mg;
    cudaGetSymbolAddress((void**)&E0, g_E0); cudaGetSymbolAddress((void**)&E1, g_E1);
    cudaGetSymbolAddress((void**)&W0, g_W0); cudaGetSymbolAddress((void**)&W1, g_W1);
    cudaGetSymbolAddress((void**)&Q0, g_Q0); cudaGetSymbolAddress((void**)&Q1, g_Q1);
    cudaGetSymbolAddress((void**)&K0, g_K0); cudaGetSymbolAddress((void**)&K1, g_K1);
    cudaGetSymbolAddress((void**)&V0, g_Vt0); cudaGetSymbolAddress((void**)&V1, g_Vt1);
    cudaGetSymbolAddress((void**)&sE, g_sE); cudaGetSymbolAddress((void**)&sW, g_sW);
    cudaGetSymbolAddress((void**)&sQ, g_sQ); cudaGetSymbolAddress((void**)&sK, g_sK);
    cudaGetSymbolAddress((void**)&sV, g_sVt);
    cudaGetSymbolAddress((void**)&Qf, g_Qf); cudaGetSymbolAddress((void**)&Kf, g_Kf);
    cudaGetSymbolAddress((void**)&Vf, g_Vtf);
    cudaGetSymbolAddress((void**)&mg, g_mags);

    quant_rows<<<BATCH * SEQ, 256>>>(E, E0, E1, sE, DMODEL, mg);   // mags fused
    quant_rows<<<DMODEL, 256>>>(Wq, W0, W1, sW, DMODEL, nullptr);
    quant_rows<<<DMODEL, 256>>>(Wk, W0 + (size_t)DMODEL * DMODEL,
                                W1 + (size_t)DMODEL * DMODEL, sW + DMODEL, DMODEL, nullptr);
    quant_rows<<<DMODEL, 256>>>(Wv, W0 + 2 * (size_t)DMODEL * DMODEL,
                                W1 + 2 * (size_t)DMODEL * DMODEL, sW + 2 * DMODEL, DMODEL, nullptr);

    thresh_kernel<<<1, 256>>>();

    dim3 gQKV(DMODEL / 128, (BATCH * SEQ) / 128, 3);
    qkv_tc<<<gQKV, NTHREADS, SMEM_TOTAL>>>();

    quant_rows<<<BATCH * SEQ, 256>>>(Qf, Q0, Q1, sQ, DMODEL, nullptr);
    quant_rows<<<BATCH * SEQ, 256>>>(Kf, K0, K1, sK, DMODEL, nullptr);
    quant_rows<<<BATCH * DMODEL, 256>>>(Vf, V0, V1, sV, SEQ, nullptr);

    dim3 gS(SEQ / 128, SEQ / 128, BATCH);
    scores_tc<<<gS, NTHREADS, SMEM_TOTAL>>>(bias, mask, wts);

    softmax_kernel<<<BATCH * SEQ, 256>>>(wts);

    dim3 gAV(DMODEL / 128, SEQ / 128, BATCH);
    av_tc<<<gAV, NTHREADS, SMEM_TOTAL>>>(att);
}

// round 16
// speedup vs baseline: 1.2374x; 1.0390x over previous
#include <cuda_runtime.h>
#include <cuda_fp16.h>
#include <cstdint>
#include <math.h>

#define BATCH 4
#define SEQ   2048
#define DMODEL 1024

// smem: BK=128 int8 -> 128B rows; planes A0|A1|B0|B1 16KB each; 3 stages
#define PLANE_BYTES  16384
#define STAGE_BYTES  (4 * PLANE_BYTES)      // 64KB
#define NSTAGE       3
#define SMEM_TOTAL   (NSTAGE * STAGE_BYTES) // 192KB
#define NTHREADS     512

// ======================= scratch ============================================
__device__ __align__(16) char g_E0[BATCH * SEQ * DMODEL];
__device__ __align__(16) char g_E1[BATCH * SEQ * DMODEL];
__device__ __align__(16) char g_W0[3 * DMODEL * DMODEL];
__device__ __align__(16) char g_W1[3 * DMODEL * DMODEL];
__device__ __align__(16) char g_Q0[BATCH * SEQ * DMODEL];
__device__ __align__(16) char g_Q1[BATCH * SEQ * DMODEL];
__device__ __align__(16) char g_K0[BATCH * SEQ * DMODEL];
__device__ __align__(16) char g_K1[BATCH * SEQ * DMODEL];
__device__ __align__(16) char g_Vt0[BATCH * DMODEL * SEQ];   // [b][d][s]
__device__ __align__(16) char g_Vt1[BATCH * DMODEL * SEQ];
__device__ __align__(16) char g_P0[BATCH * SEQ * SEQ];
__device__ __align__(16) char g_P1[BATCH * SEQ * SEQ];
__device__ __align__(16) __half g_Qh[BATCH * SEQ * DMODEL];  // fp16 staging
__device__ __align__(16) __half g_Kh[BATCH * SEQ * DMODEL];
__device__ __align__(16) __half g_Vth[BATCH * DMODEL * SEQ];
__device__ float g_sE[BATCH * SEQ];
__device__ float g_sW[3 * DMODEL];
__device__ float g_sQ[BATCH * SEQ];
__device__ float g_sK[BATCH * SEQ];
__device__ float g_sVt[BATCH * DMODEL];
__device__ float g_sP[BATCH * SEQ];
__device__ float g_mags[BATCH * SEQ];
__device__ float g_thresh;

__device__ __forceinline__ uint32_t smem_u32(const void* p) {
    uint32_t a;
    asm("{ .reg .u64 t; cvta.to.shared.u64 t, %1; cvt.u32.u64 %0, t; }" : "=r"(a) : "l"(p));
    return a;
}
__device__ __forceinline__ void cp16(uint32_t dst, const void* src) {
    asm volatile("cp.async.cg.shared.global [%0], [%1], 16;" :: "r"(dst), "l"(src));
}
#define CP_COMMIT() asm volatile("cp.async.commit_group;" ::: "memory")
#define CP_WAIT1()  asm volatile("cp.async.wait_group 1;" ::: "memory")
#define CP_WAIT0()  asm volatile("cp.async.wait_group 0;" ::: "memory")

__device__ __forceinline__ void ldm4(uint32_t f[4], uint32_t addr) {
    asm volatile("ldmatrix.sync.aligned.m8n8.x4.shared.b16 {%0,%1,%2,%3}, [%4];"
        : "=r"(f[0]), "=r"(f[1]), "=r"(f[2]), "=r"(f[3]) : "r"(addr));
}
__device__ __forceinline__ void imma(int c[4], const uint32_t a[4],
                                     uint32_t b0, uint32_t b1) {
    asm volatile(
        "mma.sync.aligned.m16n8k32.row.col.s32.s8.s8.s32 "
        "{%0,%1,%2,%3}, {%4,%5,%6,%7}, {%8,%9}, {%0,%1,%2,%3};"
        : "+r"(c[0]), "+r"(c[1]), "+r"(c[2]), "+r"(c[3])
        : "r"(a[0]), "r"(a[1]), "r"(a[2]), "r"(a[3]), "r"(b0), "r"(b1));
}

__device__ __forceinline__ void quant2(float x, float inv, char& q0, char& q1) {
    float t = x * inv;
    int a = __float2int_rn(t);
    int b = __float2int_rn((t - (float)a) * 128.0f);
    q0 = (char)a;
    q1 = (char)b;
}

// ======================= quantize rows (fp32 src, + optional L2 norm) =======
__device__ __forceinline__ void quant_body_f32(
    const float* __restrict__ src, char* __restrict__ L0, char* __restrict__ L1,
    float* __restrict__ scl, int C, float* __restrict__ mags_out, int row)
{
    int tid = threadIdx.x;
    const float4* p = (const float4*)(src + (size_t)row * C);
    int n4 = C >> 2;
    float mx = 0.0f, sq = 0.0f;
    for (int i = tid; i < n4; i += 256) {
        float4 v = p[i];
        mx = fmaxf(mx, fmaxf(fmaxf(fabsf(v.x), fabsf(v.y)),
                             fmaxf(fabsf(v.z), fabsf(v.w))));
        if (mags_out) sq += v.x * v.x + v.y * v.y + v.z * v.z + v.w * v.w;
    }
    __shared__ float sm[256];
    __shared__ float ss[256];
    sm[tid] = mx;
    ss[tid] = sq;
    __syncthreads();
    for (int off = 128; off > 0; off >>= 1) {
        if (tid < off) {
            sm[tid] = fmaxf(sm[tid], sm[tid + off]);
            ss[tid] += ss[tid + off];
        }
        __syncthreads();
    }
    float s = sm[0] * (1.0f / 127.0f);
    float inv = (s > 0.0f) ? 1.0f / s : 0.0f;
    if (tid == 0) {
        scl[row] = (s > 0.0f) ? s : 1.0f;
        if (mags_out) mags_out[row] = sqrtf(ss[0]);
    }
    char* l0 = L0 + (size_t)row * C;
    char* l1 = L1 + (size_t)row * C;
    for (int i = tid; i < n4; i += 256) {
        float4 v = p[i];
        char a0, a1, b0, b1, c0, c1, d0, d1;
        quant2(v.x, inv, a0, a1); quant2(v.y, inv, b0, b1);
        quant2(v.z, inv, c0, c1); quant2(v.w, inv, d0, d1);
        ((char4*)l0)[i] = make_char4(a0, b0, c0, d0);
        ((char4*)l1)[i] = make_char4(a1, b1, c1, d1);
    }
}

__global__ void quant_E(const float* __restrict__ E) {
    quant_body_f32(E, g_E0, g_E1, g_sE, DMODEL, g_mags, blockIdx.x);
}

__global__ void quant_W(const float* __restrict__ Wq, const float* __restrict__ Wk,
                        const float* __restrict__ Wv) {
    int y = blockIdx.y;
    const float* src = (y == 0) ? Wq : (y == 1) ? Wk : Wv;
    quant_body_f32(src, g_W0 + (size_t)y * DMODEL * DMODEL,
                   g_W1 + (size_t)y * DMODEL * DMODEL,
                   g_sW + y * DMODEL, DMODEL, nullptr, blockIdx.x);
}

// ======================= quantize rows (fp16 src) ===========================
__device__ __forceinline__ void quant_body_f16(
    const __half* __restrict__ src, char* __restrict__ L0, char* __restrict__ L1,
    float* __restrict__ scl, int C, int row)
{
    int tid = threadIdx.x;
    const __half2* p = (const __half2*)(src + (size_t)row * C);
    int n2 = C >> 1;
    float mx = 0.0f;
    for (int i = tid; i < n2; i += 256) {
        float2 f = __half22float2(p[i]);
        mx = fmaxf(mx, fmaxf(fabsf(f.x), fabsf(f.y)));
    }
    __shared__ float sm[256];
    sm[tid] = mx;
    __syncthreads();
    for (int off = 128; off > 0; off >>= 1) {
        if (tid < off) sm[tid] = fmaxf(sm[tid], sm[tid + off]);
        __syncthreads();
    }
    float s = sm[0] * (1.0f / 127.0f);
    float inv = (s > 0.0f) ? 1.0f / s : 0.0f;
    if (tid == 0) scl[row] = (s > 0.0f) ? s : 1.0f;
    char* l0 = L0 + (size_t)row * C;
    char* l1 = L1 + (size_t)row * C;
    int n4 = C >> 2;
    for (int i = tid; i < n4; i += 256) {
        float2 fa = __half22float2(p[i * 2]);
        float2 fb = __half22float2(p[i * 2 + 1]);
        char a0, a1, b0, b1, c0, c1, d0, d1;
        quant2(fa.x, inv, a0, a1); quant2(fa.y, inv, b0, b1);
        quant2(fb.x, inv, c0, c1); quant2(fb.y, inv, d0, d1);
        ((char4*)l0)[i] = make_char4(a0, b0, c0, d0);
        ((char4*)l1)[i] = make_char4(a1, b1, c1, d1);
    }
}

__global__ void quant_QK() {
    if (blockIdx.y == 0)
        quant_body_f16(g_Qh, g_Q0, g_Q1, g_sQ, DMODEL, blockIdx.x);
    else
        quant_body_f16(g_Kh, g_K0, g_K1, g_sK, DMODEL, blockIdx.x);
}
__global__ void quant_Vt() {
    quant_body_f16(g_Vth, g_Vt0, g_Vt1, g_sVt, SEQ, blockIdx.x);
}

__global__ void thresh_kernel() {
    int tid = threadIdx.x;
    __shared__ double sd[256];
    double total = 0.0;
    for (int b = 0; b < BATCH; b++) {
        double local = 0.0;
        for (int i = tid; i < SEQ; i += 256) local += (double)g_mags[b * SEQ + i];
        sd[tid] = local;
        __syncthreads();
        for (int off = 128; off > 0; off >>= 1) {
            if (tid < off) sd[tid] += sd[tid + off];
            __syncthreads();
        }
        if (tid == 0) total += sd[0] * sd[0];
        __syncthreads();
    }
    if (tid == 0) g_thresh = (float)(total / ((double)BATCH * SEQ * SEQ));
}

// ======================= softmax (+ inline P quantization) ==================
__global__ void softmax_kernel(float* __restrict__ w) {
    size_t row = blockIdx.x;
    float4* p = (float4*)(w + row * SEQ);
    int tid = threadIdx.x;
    float4 v0 = p[tid];
    float4 v1 = p[tid + 256];
    float m = fmaxf(fmaxf(fmaxf(v0.x, v0.y), fmaxf(v0.z, v0.w)),
                    fmaxf(fmaxf(v1.x, v1.y), fmaxf(v1.z, v1.w)));
    __shared__ float sm[256];
    sm[tid] = m;
    __syncthreads();
    for (int off = 128; off > 0; off >>= 1) {
        if (tid < off) sm[tid] = fmaxf(sm[tid], sm[tid + off]);
        __syncthreads();
    }
    m = sm[0];
    __syncthreads();
    v0.x = expf(v0.x - m); v0.y = expf(v0.y - m);
    v0.z = expf(v0.z - m); v0.w = expf(v0.w - m);
    v1.x = expf(v1.x - m); v1.y = expf(v1.y - m);
    v1.z = expf(v1.z - m); v1.w = expf(v1.w - m);
    float s = v0.x + v0.y + v0.z + v0.w + v1.x + v1.y + v1.z + v1.w;
    sm[tid] = s;
    __syncthreads();
    for (int off = 128; off > 0; off >>= 1) {
        if (tid < off) sm[tid] += sm[tid + off];
        __syncthreads();
    }
    float inv = 1.0f / sm[0];
    if (tid == 0) g_sP[row] = inv * (1.0f / 127.0f);

    char q0[8], q1[8];
    quant2(v0.x * 127.0f, 1.0f, q0[0], q1[0]);
    quant2(v0.y * 127.0f, 1.0f, q0[1], q1[1]);
    quant2(v0.z * 127.0f, 1.0f, q0[2], q1[2]);
    quant2(v0.w * 127.0f, 1.0f, q0[3], q1[3]);
    quant2(v1.x * 127.0f, 1.0f, q0[4], q1[4]);
    quant2(v1.y * 127.0f, 1.0f, q0[5], q1[5]);
    quant2(v1.z * 127.0f, 1.0f, q0[6], q1[6]);
    quant2(v1.w * 127.0f, 1.0f, q0[7], q1[7]);
    ((char4*)(g_P0 + row * SEQ))[tid] = make_char4(q0[0], q0[1], q0[2], q0[3]);
    ((char4*)(g_P1 + row * SEQ))[tid] = make_char4(q1[0], q1[1], q1[2], q1[3]);
    ((char4*)(g_P0 + row * SEQ))[tid + 256] = make_char4(q0[4], q0[5], q0[6], q0[7]);
    ((char4*)(g_P1 + row * SEQ))[tid + 256] = make_char4(q1[4], q1[5], q1[6], q1[7]);

    v0.x *= inv; v0.y *= inv; v0.z *= inv; v0.w *= inv;
    v1.x *= inv; v1.y *= inv; v1.z *= inv; v1.w *= inv;
    p[tid] = v0;
    p[tid + 256] = v1;
}

// ======================= pipelined IMMA GEMM core ===========================
// C[128x128]/CTA, 16 warps (4x4) each 32x32, BK=128 int8, 3-stage ring.
__device__ __forceinline__ void load_stage(
    uint32_t sb, int slot, int row, int qs,
    const char* __restrict__ A0, const char* __restrict__ A1,
    const char* __restrict__ B0, const char* __restrict__ B1,
    int lda, int ldb, int m0, int n0, int k0)
{
    uint32_t drow = sb + (uint32_t)slot * STAGE_BYTES + (uint32_t)row * 128;
    const char* a0 = A0 + (size_t)(m0 + row) * lda + k0;
    const char* a1 = A1 + (size_t)(m0 + row) * lda + k0;
    const char* b0 = B0 + (size_t)(n0 + row) * ldb + k0;
    const char* b1 = B1 + (size_t)(n0 + row) * ldb + k0;
    #pragma unroll
    for (int i = 0; i < 2; i++) {
        int seg = qs * 2 + i;
        uint32_t sw = (uint32_t)((seg ^ (row & 7)) * 16);
        cp16(drow + sw,                   a0 + seg * 16);
        cp16(drow + sw + PLANE_BYTES,     a1 + seg * 16);
        cp16(drow + sw + 2 * PLANE_BYTES, b0 + seg * 16);
        cp16(drow + sw + 3 * PLANE_BYTES, b1 + seg * 16);
    }
}

__device__ __forceinline__ void gemm_run(
    const char* __restrict__ A0, const char* __restrict__ A1,
    const char* __restrict__ B0, const char* __restrict__ B1,
    int lda, int ldb, int K, int m0, int n0,
    int acc0[2][4][4], int accX[2][4][4])
{
    extern __shared__ __align__(16) char smem[];
    uint32_t sb = smem_u32(smem);
    int tid = threadIdx.x, lane = tid & 31, warp = tid >> 5;
    int wm = (warp >> 2) * 32, wn = (warp & 3) * 32;
    int row = tid >> 2, qs = tid & 3;
    int g = lane >> 3, r = lane & 7;
    int rb = (g & 1) * 8 + r, hsel = g >> 1;

    int NC = K >> 7;   // BK=128 int8
    #pragma unroll
    for (int s = 0; s < NSTAGE - 1; s++) {
        load_stage(sb, s, row, qs, A0, A1, B0, B1, lda, ldb, m0, n0, s * 128);
        CP_COMMIT();
    }

    uint32_t arow = (uint32_t)((wm + rb) * 128);
    uint32_t brow = (uint32_t)((wn + rb) * 128);

    for (int c = 0; c < NC; c++) {
        if (c == NC - 1) CP_WAIT0(); else CP_WAIT1();   // last chunk fully resident
        __syncthreads();
        if (c + 2 < NC) {
            load_stage(sb, (c + 2) % NSTAGE, row, qs, A0, A1, B0, B1,
                       lda, ldb, m0, n0, (c + 2) * 128);
            CP_COMMIT();
        }
        uint32_t st = sb + (uint32_t)(c % NSTAGE) * STAGE_BYTES;
        #pragma unroll
        for (int kb = 0; kb < 4; kb++) {
            uint32_t segoff = (uint32_t)((((kb * 2) | hsel) ^ r) * 16);
            uint32_t a0f[2][4], a1f[2][4], b0f[2][4], b1f[2][4];
            #pragma unroll
            for (int mi = 0; mi < 2; mi++) {
                uint32_t ad = st + arow + (uint32_t)(mi * 16 * 128) + segoff;
                ldm4(a0f[mi], ad);
                ldm4(a1f[mi], ad + PLANE_BYTES);
            }
            #pragma unroll
            for (int nb = 0; nb < 2; nb++) {
                uint32_t bd = st + 2 * PLANE_BYTES + brow + (uint32_t)(nb * 16 * 128) + segoff;
                ldm4(b0f[nb], bd);
                ldm4(b1f[nb], bd + PLANE_BYTES);
            }
            #pragma unroll
            for (int mi = 0; mi < 2; mi++)
                #pragma unroll
                for (int nb = 0; nb < 2; nb++)
                    #pragma unroll
                    for (int s = 0; s < 2; s++) {
                        int ni = nb * 2 + s;
                        imma(acc0[mi][ni], a0f[mi], b0f[nb][s], b0f[nb][s + 2]);
                        imma(accX[mi][ni], a0f[mi], b1f[nb][s], b1f[nb][s + 2]);
                        imma(accX[mi][ni], a1f[mi], b0f[nb][s], b0f[nb][s + 2]);
                    }
        }
    }
}

#define COMBINE(mi, ni, j) ((float)acc0[mi][ni][j] + (float)accX[mi][ni][j] * 0.0078125f)

// ======================= GEMM kernels =======================================
__global__ void __launch_bounds__(NTHREADS, 1) qkv_tc() {
    int z = blockIdx.z;
    const char* Bw0 = g_W0 + (size_t)z * DMODEL * DMODEL;
    const char* Bw1 = g_W1 + (size_t)z * DMODEL * DMODEL;
    int m0 = blockIdx.y * 128, n0 = blockIdx.x * 128;
    int acc0[2][4][4] = {}, accX[2][4][4] = {};
    gemm_run(g_E0, g_E1, Bw0, Bw1, DMODEL, DMODEL, DMODEL, m0, n0, acc0, accX);

    int lane = threadIdx.x & 31, warp = threadIdx.x >> 5;
    int wm = (warp >> 2) * 32, wn = (warp & 3) * 32;
    #pragma unroll
    for (int mi = 0; mi < 2; mi++)
        #pragma unroll
        for (int h = 0; h < 2; h++) {
            int rg = m0 + wm + mi * 16 + h * 8 + (lane >> 2);
            float sa = g_sE[rg];
            #pragma unroll
            for (int ni = 0; ni < 4; ni++) {
                int col = n0 + wn + ni * 8 + (lane & 3) * 2;
                float sb0 = g_sW[z * DMODEL + col];
                float sb1 = g_sW[z * DMODEL + col + 1];
                float x0 = sa * sb0 * COMBINE(mi, ni, h * 2);
                float x1 = sa * sb1 * COMBINE(mi, ni, h * 2 + 1);
                if (z == 2) {
                    int b = rg >> 11, s = rg & (SEQ - 1);
                    __half* vb = g_Vth + (size_t)b * DMODEL * SEQ;
                    vb[(size_t)col * SEQ + s] = __float2half_rn(x0);
                    vb[(size_t)(col + 1) * SEQ + s] = __float2half_rn(x1);
                } else {
                    __half* C = (z == 0) ? g_Qh : g_Kh;
                    __half2 h2 = __floats2half2_rn(x0, x1);
                    *(__half2*)&C[(size_t)rg * DMODEL + col] = h2;
                }
            }
        }
}

__global__ void __launch_bounds__(NTHREADS, 1) scores_tc(
    const float* __restrict__ intent_bias, const int* __restrict__ mask,
    float* __restrict__ wts)
{
    int b = blockIdx.z;
    size_t off = (size_t)b * SEQ * DMODEL;
    int m0 = blockIdx.y * 128, n0 = blockIdx.x * 128;
    int acc0[2][4][4] = {}, accX[2][4][4] = {};
    gemm_run(g_Q0 + off, g_Q1 + off, g_K0 + off, g_K1 + off,
             DMODEL, DMODEL, DMODEL, m0, n0, acc0, accX);

    int lane = threadIdx.x & 31, warp = threadIdx.x >> 5;
    int wm = (warp >> 2) * 32, wn = (warp & 3) * 32;
    float th = g_thresh;
    float bias = intent_bias[0];
    #pragma unroll
    for (int mi = 0; mi < 2; mi++)
        #pragma unroll
        for (int h = 0; h < 2; h++) {
            int q = m0 + wm + mi * 16 + h * 8 + (lane >> 2);
            float mq = g_mags[b * SEQ + q];
            float sa = g_sQ[b * SEQ + q] * 0.03125f;
            size_t rb2 = ((size_t)b * SEQ + q) * SEQ;
            #pragma unroll
            for (int ni = 0; ni < 4; ni++) {
                int col = n0 + wn + ni * 8 + (lane & 3) * 2;
                float x0 = sa * g_sK[b * SEQ + col] * COMBINE(mi, ni, h * 2);
                float x1 = sa * g_sK[b * SEQ + col + 1] * COMBINE(mi, ni, h * 2 + 1);
                float mk0 = g_mags[b * SEQ + col];
                float mk1 = g_mags[b * SEQ + col + 1];
                if (mq * mk0 > th) x0 += bias;
                if (mq * mk1 > th) x1 += bias;
                int2 mv = *(const int2*)&mask[rb2 + col];
                if (mv.x == 0) x0 = -1e9f;
                if (mv.y == 0) x1 = -1e9f;
                *(float2*)&wts[rb2 + col] = make_float2(x0, x1);
            }
        }
}

__global__ void __launch_bounds__(NTHREADS, 1) av_tc(float* __restrict__ att) {
    int b = blockIdx.z;
    size_t po = (size_t)b * SEQ * SEQ;
    size_t vo = (size_t)b * DMODEL * SEQ;
    int m0 = blockIdx.y * 128, n0 = blockIdx.x * 128;
    int acc0[2][4][4] = {}, accX[2][4][4] = {};
    gemm_run(g_P0 + po, g_P1 + po, g_Vt0 + vo, g_Vt1 + vo,
             SEQ, SEQ, SEQ, m0, n0, acc0, accX);

    int lane = threadIdx.x & 31, warp = threadIdx.x >> 5;
    int wm = (warp >> 2) * 32, wn = (warp & 3) * 32;
    #pragma unroll
    for (int mi = 0; mi < 2; mi++)
        #pragma unroll
        for (int h = 0; h < 2; h++) {
            int s = m0 + wm + mi * 16 + h * 8 + (lane >> 2);
            float sa = g_sP[b * SEQ + s];
            #pragma unroll
            for (int ni = 0; ni < 4; ni++) {
                int col = n0 + wn + ni * 8 + (lane & 3) * 2;
                float x0 = sa * g_sVt[b * DMODEL + col] * COMBINE(mi, ni, h * 2);
                float x1 = sa * g_sVt[b * DMODEL + col + 1] * COMBINE(mi, ni, h * 2 + 1);
                *(float2*)&att[((size_t)b * SEQ + s) * DMODEL + col] =
                    make_float2(x0, x1);
            }
        }
}

// ======================= launch =============================================
extern "C" void kernel_launch(void* const* d_in, const int* in_sizes, int n_in,
                              void* d_out, int out_size)
{
    (void)in_sizes; (void)n_in; (void)out_size;
    const float* E    = (const float*)d_in[0];
    const float* Wq   = (const float*)d_in[1];
    const float* Wk   = (const float*)d_in[2];
    const float* Wv   = (const float*)d_in[3];
    const float* bias = (const float*)d_in[4];
    const int*   mask = (const int*)d_in[5];

    float* out = (float*)d_out;
    float* att = out;                                  // [B,S,D]
    float* wts = out + (size_t)BATCH * SEQ * DMODEL;   // [B,S,S]

    cudaFuncSetAttribute(qkv_tc,    cudaFuncAttributeMaxDynamicSharedMemorySize, SMEM_TOTAL);
    cudaFuncSetAttribute(scores_tc, cudaFuncAttributeMaxDynamicSharedMemorySize, SMEM_TOTAL);
    cudaFuncSetAttribute(av_tc,     cudaFuncAttributeMaxDynamicSharedMemorySize, SMEM_TOTAL);

    quant_E<<<BATCH * SEQ, 256>>>(E);                      // E planes + mags
    quant_W<<<dim3(DMODEL, 3), 256>>>(Wq, Wk, Wv);         // all 3 weights
    thresh_kernel<<<1, 256>>>();

    dim3 gQKV(DMODEL / 128, (BATCH * SEQ) / 128, 3);
    qkv_tc<<<gQKV, NTHREADS, SMEM_TOTAL>>>();

    quant_QK<<<dim3(BATCH * SEQ, 2), 256>>>();             // Q + K planes
    quant_Vt<<<BATCH * DMODEL, 256>>>();                   // Vt planes

    dim3 gS(SEQ / 128, SEQ / 128, BATCH);
    scores_tc<<<gS, NTHREADS, SMEM_TOTAL>>>(bias, mask, wts);

    softmax_kernel<<<BATCH * SEQ, 256>>>(wts);

    dim3 gAV(DMODEL / 128, SEQ / 128, BATCH);
    av_tc<<<gAV, NTHREADS, SMEM_TOTAL>>>(att);
}